// round 15
// baseline (speedup 1.0000x reference)
#include <cuda_runtime.h>

// Problem constants (fixed by the reference).
#define BN 4096
#define DN 768
#define KN 60
#define NLOGITS 61   // [pos, 60 negs]
#define NW 192       // int32 words per row (768 int8)
#define ROWS_PER_CTA 4
#define GRID (BN / ROWS_PER_CTA)   // 1024

// Word->dim mapping (shared by quantizer and main kernel):
//   lane l owns words 4l..4l+3   (dims 16l .. 16l+15)      -> int4 chunk
//   and   words 128+2l..128+2l+1 (dims 512+8l .. 512+8l+7) -> int2 chunk

// Scratch (__device__ globals: no allocation allowed).
__device__ __align__(256) int g_item_i8[BN * NW];   // 3 MB int8 item table
__device__ float g_item_scale[BN];                  // per-row max/127
__device__ float g_row_loss[BN];
__device__ int   g_ctr = 0;

// ---------------------------------------------------------------------------
// Prologue: per-row symmetric int8 quantization of the ITEM table only.
// One warp per row. Stores via STG.128 + STG.64.
// ---------------------------------------------------------------------------
__global__ void __launch_bounds__(256)
quantize_items_kernel(const float* __restrict__ item_emb)
{
    const int row  = (blockIdx.x * 256 + threadIdx.x) >> 5;   // 0 .. BN-1
    const int lane = threadIdx.x & 31;

    const float4* s4 = reinterpret_cast<const float4*>(item_emb + (size_t)row * DN);
    float4 v[6];
    #pragma unroll
    for (int k = 0; k < 4; ++k) v[k] = __ldg(&s4[4 * lane + k]);        // dims 16l..16l+15
    #pragma unroll
    for (int k = 0; k < 2; ++k) v[4 + k] = __ldg(&s4[128 + 2 * lane + k]); // dims 512+8l..

    float m = 0.0f;
    #pragma unroll
    for (int t = 0; t < 6; ++t)
        m = fmaxf(m, fmaxf(fmaxf(fabsf(v[t].x), fabsf(v[t].y)),
                           fmaxf(fabsf(v[t].z), fabsf(v[t].w))));
    #pragma unroll
    for (int o = 16; o > 0; o >>= 1)
        m = fmaxf(m, __shfl_xor_sync(0xffffffffu, m, o));
    m = fmaxf(m, 1e-20f);
    const float inv = 127.0f / m;

    int q[6];
    #pragma unroll
    for (int t = 0; t < 6; ++t) {
        const int qx = __float2int_rn(v[t].x * inv);
        const int qy = __float2int_rn(v[t].y * inv);
        const int qz = __float2int_rn(v[t].z * inv);
        const int qw = __float2int_rn(v[t].w * inv);
        q[t] = (qx & 0xFF) | ((qy & 0xFF) << 8) | ((qz & 0xFF) << 16) | (qw << 24);
    }

    int* dst = g_item_i8 + (size_t)row * NW;
    *reinterpret_cast<int4*>(dst + 4 * lane) = make_int4(q[0], q[1], q[2], q[3]);
    *reinterpret_cast<int2*>(dst + 128 + 2 * lane) = make_int2(q[4], q[5]);
    if (lane == 0) g_item_scale[row] = m / 127.0f;
}

// ---------------------------------------------------------------------------
// Main: ONE WARP PER ROW (4 warps/CTA, grid 1024). Fused in-warp user
// quantization; 31 fully-unrolled pair-iterations; int4+int2 gathers;
// paired 6-shfl reductions; in-warp logsumexp.
// ---------------------------------------------------------------------------
__global__ void __launch_bounds__(128, 6)
u2i_loss_kernel(const float* __restrict__ user_emb,
                const int*   __restrict__ neg_idx,
                float*       __restrict__ out)
{
    __shared__ int   s_idx[ROWS_PER_CTA * 64];
    __shared__ float s_scale[ROWS_PER_CTA * 64];
    __shared__ float slog[ROWS_PER_CTA * 64];
    __shared__ int   s_last;

    const int tid  = threadIdx.x;
    const int warp = tid >> 5;
    const int lane = tid & 31;
    const int row  = blockIdx.x * ROWS_PER_CTA + warp;
    const int base = warp * 64;

    // Per-warp prologue: 61 indices + scales into warp-private smem.
    if (lane < 30) {
        const int2 v = __ldg(reinterpret_cast<const int2*>(neg_idx + (size_t)row * KN + 2 * lane));
        s_idx[base + 1 + 2 * lane] = v.x;
        s_idx[base + 2 + 2 * lane] = v.y;
        s_scale[base + 1 + 2 * lane] = __ldg(&g_item_scale[v.x]);
        s_scale[base + 2 + 2 * lane] = __ldg(&g_item_scale[v.y]);
    } else if (lane == 30) {
        s_idx[base] = row;                             // logit 0 = positive
        s_scale[base] = __ldg(&g_item_scale[row]);
    } else {
        s_idx[base + 61] = 0; s_idx[base + 62] = 0; s_idx[base + 63] = 0;
        slog[base + 61] = -3.0e38f;
        slog[base + 62] = -3.0e38f;
        slog[base + 63] = -3.0e38f;
    }

    // Fused user quantization (identical mapping + formula as item table).
    const float4* uf = reinterpret_cast<const float4*>(user_emb + (size_t)row * DN);
    float4 w[6];
    #pragma unroll
    for (int k = 0; k < 4; ++k) w[k] = __ldg(&uf[4 * lane + k]);
    #pragma unroll
    for (int k = 0; k < 2; ++k) w[4 + k] = __ldg(&uf[128 + 2 * lane + k]);

    float m = 0.0f;
    #pragma unroll
    for (int t = 0; t < 6; ++t)
        m = fmaxf(m, fmaxf(fmaxf(fabsf(w[t].x), fabsf(w[t].y)),
                           fmaxf(fabsf(w[t].z), fabsf(w[t].w))));
    #pragma unroll
    for (int o = 16; o > 0; o >>= 1)
        m = fmaxf(m, __shfl_xor_sync(0xffffffffu, m, o));
    m = fmaxf(m, 1e-20f);
    const float su  = m / 127.0f;
    const float inv = 127.0f / m;

    int u[6];
    #pragma unroll
    for (int t = 0; t < 6; ++t) {
        const int qx = __float2int_rn(w[t].x * inv);
        const int qy = __float2int_rn(w[t].y * inv);
        const int qz = __float2int_rn(w[t].z * inv);
        const int qw = __float2int_rn(w[t].w * inv);
        u[t] = (qx & 0xFF) | ((qy & 0xFF) << 8) | ((qz & 0xFF) << 16) | (qw << 24);
    }
    __syncwarp();

    // 31 pair-iterations, CONSTANT trip count (full unroll is load-bearing).
    #pragma unroll
    for (int p = 0; p < 31; ++p) {
        const int jA = 2 * p;
        const int jB = 2 * p + 1;
        const int* rA = g_item_i8 + (size_t)s_idx[base + jA] * NW;
        const int* rB = g_item_i8 + (size_t)s_idx[base + jB] * NW;

        const int4 a4 = __ldg(reinterpret_cast<const int4*>(rA + 4 * lane));
        const int2 a2 = __ldg(reinterpret_cast<const int2*>(rA + 128 + 2 * lane));
        const int4 b4 = __ldg(reinterpret_cast<const int4*>(rB + 4 * lane));
        const int2 b2 = __ldg(reinterpret_cast<const int2*>(rB + 128 + 2 * lane));

        int accA = 0, accB = 0;
        accA = __dp4a(a4.x, u[0], accA);
        accA = __dp4a(a4.y, u[1], accA);
        accA = __dp4a(a4.z, u[2], accA);
        accA = __dp4a(a4.w, u[3], accA);
        accA = __dp4a(a2.x, u[4], accA);
        accA = __dp4a(a2.y, u[5], accA);
        accB = __dp4a(b4.x, u[0], accB);
        accB = __dp4a(b4.y, u[1], accB);
        accB = __dp4a(b4.z, u[2], accB);
        accB = __dp4a(b4.w, u[3], accB);
        accB = __dp4a(b2.x, u[4], accB);
        accB = __dp4a(b2.y, u[5], accB);

        // Paired reduction: 6 shfls for both exact int sums.
        accA += __shfl_xor_sync(0xffffffffu, accA, 16);
        accB += __shfl_xor_sync(0xffffffffu, accB, 16);
        int v = (lane < 16) ? accA : accB;
        #pragma unroll
        for (int o = 8; o > 0; o >>= 1)
            v += __shfl_xor_sync(0xffffffffu, v, o);

        if (lane == 0)                  slog[base + jA] = (float)v * su * s_scale[base + jA];
        if (lane == 16 && jB < NLOGITS) slog[base + jB] = (float)v * su * s_scale[base + jB];
    }
    __syncwarp();

    // In-warp stable logsumexp over 61 logits (2 per lane; 62..63 = -inf).
    {
        const float l0 = slog[base + lane];
        const float l1 = slog[base + lane + 32];
        float mm = fmaxf(l0, l1);
        #pragma unroll
        for (int o = 16; o > 0; o >>= 1)
            mm = fmaxf(mm, __shfl_xor_sync(0xffffffffu, mm, o));
        float s = expf(l0 - mm) + ((lane + 32 < NLOGITS) ? expf(l1 - mm) : 0.0f);
        #pragma unroll
        for (int o = 16; o > 0; o >>= 1)
            s += __shfl_xor_sync(0xffffffffu, s, o);
        if (lane == 0) {
            g_row_loss[row] = logf(s) + mm - slog[base];
            __threadfence();                            // release this row's loss
        }
    }
    __syncthreads();

    // CTA ticket; the last CTA performs the deterministic mean.
    if (tid == 0) {
        __threadfence();
        const int t = atomicAdd(&g_ctr, 1);
        s_last = (t == GRID - 1);
    }
    __syncthreads();

    if (s_last) {
        __threadfence();
        __shared__ float sred[128];
        float a = 0.0f;
        #pragma unroll
        for (int i = tid; i < BN; i += 128) a += g_row_loss[i];
        sred[tid] = a;
        __syncthreads();
        #pragma unroll
        for (int st = 64; st > 0; st >>= 1) {
            if (tid < st) sred[tid] += sred[tid + st];
            __syncthreads();
        }
        if (tid == 0) {
            out[0] = sred[0] * (1.0f / (float)BN);
            g_ctr = 0;                                 // reset for next graph replay
        }
    }
}

extern "C" void kernel_launch(void* const* d_in, const int* in_sizes, int n_in,
                              void* d_out, int out_size)
{
    const float* user_emb = (const float*)d_in[0];
    const float* item_emb = (const float*)d_in[1];
    const int*   neg_idx  = (const int*)d_in[2];
    float*       out      = (float*)d_out;

    quantize_items_kernel<<<BN / 8, 256>>>(item_emb);
    u2i_loss_kernel<<<GRID, 128>>>(user_emb, neg_idx, out);
}

// round 16
// speedup vs baseline: 1.2471x; 1.2471x over previous
#include <cuda_runtime.h>

// Problem constants (fixed by the reference).
#define BN 4096
#define DN 768
#define KN 60
#define NLOGITS 61   // [pos, 60 negs]
#define NW 192       // int32 words per row (768 int8)
#define ROWS_PER_CTA 2
#define GRID (BN / ROWS_PER_CTA)   // 2048

// Scratch (__device__ globals: no allocation allowed).
__device__ __align__(256) int g_item_i8[BN * NW];   // 3 MB int8 item table
__device__ __align__(256) int g_user_i8[BN * NW];   // 3 MB int8 user table
__device__ float g_item_scale[BN];                  // per-row max/127
__device__ float g_user_scale[BN];
__device__ float g_row_loss[BN];
__device__ int   g_ctr = 0;

// ---------------------------------------------------------------------------
// Prologue: per-row symmetric int8 quantization of BOTH tables (R12 version).
// One warp per row; gwarp < BN -> item row, else user row.
// ---------------------------------------------------------------------------
__global__ void __launch_bounds__(256)
quantize_rows_kernel(const float* __restrict__ item_emb,
                     const float* __restrict__ user_emb)
{
    const int gwarp = (blockIdx.x * 256 + threadIdx.x) >> 5;   // 0 .. 2*BN-1
    const int lane  = threadIdx.x & 31;

    const float* src;
    int*   dst;
    float* sc;
    if (gwarp < BN) {
        src = item_emb + (size_t)gwarp * DN;
        dst = g_item_i8 + (size_t)gwarp * NW;
        sc  = &g_item_scale[gwarp];
    } else {
        const int r = gwarp - BN;
        src = user_emb + (size_t)r * DN;
        dst = g_user_i8 + (size_t)r * NW;
        sc  = &g_user_scale[r];
    }

    const float4* s4 = reinterpret_cast<const float4*>(src);
    float4 v[6];
    float m = 0.0f;
    #pragma unroll
    for (int t = 0; t < 6; ++t) {
        v[t] = __ldg(&s4[t * 32 + lane]);
        m = fmaxf(m, fmaxf(fmaxf(fabsf(v[t].x), fabsf(v[t].y)),
                           fmaxf(fabsf(v[t].z), fabsf(v[t].w))));
    }
    #pragma unroll
    for (int o = 16; o > 0; o >>= 1)
        m = fmaxf(m, __shfl_xor_sync(0xffffffffu, m, o));
    m = fmaxf(m, 1e-20f);
    const float inv = 127.0f / m;

    #pragma unroll
    for (int t = 0; t < 6; ++t) {
        const int qx = __float2int_rn(v[t].x * inv);
        const int qy = __float2int_rn(v[t].y * inv);
        const int qz = __float2int_rn(v[t].z * inv);
        const int qw = __float2int_rn(v[t].w * inv);
        dst[t * 32 + lane] = (qx & 0xFF) | ((qy & 0xFF) << 8) |
                             ((qz & 0xFF) << 16) | (qw << 24);
    }
    if (lane == 0) *sc = m / 127.0f;
}

// One pair-iteration body (identical math/layout to R12).
#define PAIR_BODY(p)                                                           \
    {                                                                          \
        const int jA = 2 * (p);                                                \
        const int jB = 2 * (p) + 1;                                            \
        const int2* pA = reinterpret_cast<const int2*>(                        \
            g_item_i8 + (size_t)s_idx[base + jA] * NW);                        \
        const int2* pB = reinterpret_cast<const int2*>(                        \
            g_item_i8 + (size_t)s_idx[base + jB] * NW);                        \
        const int2 a0 = __ldg(&pA[lane]);                                      \
        const int2 a1 = __ldg(&pA[32 + lane]);                                 \
        const int2 a2 = __ldg(&pA[64 + lane]);                                 \
        const int2 b0 = __ldg(&pB[lane]);                                      \
        const int2 b1 = __ldg(&pB[32 + lane]);                                 \
        const int2 b2 = __ldg(&pB[64 + lane]);                                 \
        int accA = 0, accB = 0;                                                \
        accA = __dp4a(a0.x, u[0], accA);                                       \
        accA = __dp4a(a0.y, u[1], accA);                                       \
        accA = __dp4a(a1.x, u[2], accA);                                       \
        accA = __dp4a(a1.y, u[3], accA);                                       \
        accA = __dp4a(a2.x, u[4], accA);                                       \
        accA = __dp4a(a2.y, u[5], accA);                                       \
        accB = __dp4a(b0.x, u[0], accB);                                       \
        accB = __dp4a(b0.y, u[1], accB);                                       \
        accB = __dp4a(b1.x, u[2], accB);                                       \
        accB = __dp4a(b1.y, u[3], accB);                                       \
        accB = __dp4a(b2.x, u[4], accB);                                       \
        accB = __dp4a(b2.y, u[5], accB);                                       \
        accA += __shfl_xor_sync(0xffffffffu, accA, 16);                        \
        accB += __shfl_xor_sync(0xffffffffu, accB, 16);                        \
        int v = (lane < 16) ? accA : accB;                                     \
        _Pragma("unroll")                                                      \
        for (int o = 8; o > 0; o >>= 1)                                        \
            v += __shfl_xor_sync(0xffffffffu, v, o);                           \
        if (lane == 0)                                                         \
            slog[base + jA] = (float)v * su * s_scale[base + jA];              \
        if (lane == 16 && jB < NLOGITS)                                        \
            slog[base + jB] = (float)v * su * s_scale[base + jB];              \
    }

// ---------------------------------------------------------------------------
// Main: TWO WARPS PER ROW, each with a COMPILE-TIME-CONSTANT unrolled
// half-loop (sub0: pairs 0-15, sub1: pairs 16-30). 4 warps/CTA = 2 rows;
// grid = 2048. int2 gathers, paired 6-shfl reductions, per-row logsumexp.
// ---------------------------------------------------------------------------
__global__ void __launch_bounds__(128, 10)
u2i_loss_kernel(const int* __restrict__ neg_idx,
                float*     __restrict__ out)
{
    __shared__ int   s_idx[ROWS_PER_CTA * 64];
    __shared__ float s_scale[ROWS_PER_CTA * 64];
    __shared__ float slog[ROWS_PER_CTA * 64];
    __shared__ int   s_last;

    const int tid  = threadIdx.x;
    const int warp = tid >> 5;
    const int lane = tid & 31;
    const int lrow = warp >> 1;           // 0..1: row within CTA
    const int sub  = warp & 1;            // 0: pairs 0-15, 1: pairs 16-30
    const int row  = blockIdx.x * ROWS_PER_CTA + lrow;
    const int base = lrow * 64;

    // Row prologue: the row's two warps jointly fill 64 index/scale slots.
    {
        const int j = sub * 32 + lane;    // 0..63
        if (j == 0) {
            s_idx[base]   = row;          // logit 0 = positive
            s_scale[base] = __ldg(&g_item_scale[row]);
        } else if (j < NLOGITS) {
            const int it = __ldg(&neg_idx[(size_t)row * KN + j - 1]);
            s_idx[base + j]   = it;
            s_scale[base + j] = __ldg(&g_item_scale[it]);
        } else {
            s_idx[base + j] = 0;
            slog[base + j]  = -3.0e38f;
        }
    }

    // User slice: 6 int32 words (3 x LDG.64) + scale (dup per warp; L1 hits).
    const int2* uq2 = reinterpret_cast<const int2*>(g_user_i8 + (size_t)row * NW);
    int u[6];
    #pragma unroll
    for (int t = 0; t < 3; ++t) {
        const int2 w = __ldg(&uq2[t * 32 + lane]);
        u[2 * t]     = w.x;
        u[2 * t + 1] = w.y;
    }
    const float su = __ldg(&g_user_scale[row]);
    __syncthreads();

    // Constant-bound unrolled half loops (warp-uniform branch).
    if (sub == 0) {
        #pragma unroll
        for (int p = 0; p < 16; ++p) PAIR_BODY(p)
    } else {
        #pragma unroll
        for (int p = 16; p < 31; ++p) PAIR_BODY(p)
    }
    __syncthreads();

    // Sub-warp 0 of each row: stable logsumexp over 61 logits (2 per lane).
    if (sub == 0) {
        const float l0 = slog[base + lane];
        const float l1 = slog[base + lane + 32];
        float m = fmaxf(l0, l1);
        #pragma unroll
        for (int o = 16; o > 0; o >>= 1)
            m = fmaxf(m, __shfl_xor_sync(0xffffffffu, m, o));
        float s = expf(l0 - m) + ((lane + 32 < NLOGITS) ? expf(l1 - m) : 0.0f);
        #pragma unroll
        for (int o = 16; o > 0; o >>= 1)
            s += __shfl_xor_sync(0xffffffffu, s, o);
        if (lane == 0) {
            g_row_loss[row] = logf(s) + m - slog[base];
            __threadfence();                            // release this row's loss
        }
    }
    __syncthreads();

    // CTA ticket; the last CTA performs the deterministic mean.
    if (tid == 0) {
        __threadfence();
        const int t = atomicAdd(&g_ctr, 1);
        s_last = (t == GRID - 1);
    }
    __syncthreads();

    if (s_last) {
        __threadfence();
        __shared__ float sred[128];
        float a = 0.0f;
        #pragma unroll
        for (int i = tid; i < BN; i += 128) a += g_row_loss[i];
        sred[tid] = a;
        __syncthreads();
        #pragma unroll
        for (int st = 64; st > 0; st >>= 1) {
            if (tid < st) sred[tid] += sred[tid + st];
            __syncthreads();
        }
        if (tid == 0) {
            out[0] = sred[0] * (1.0f / (float)BN);
            g_ctr = 0;                                 // reset for next graph replay
        }
    }
}

extern "C" void kernel_launch(void* const* d_in, const int* in_sizes, int n_in,
                              void* d_out, int out_size)
{
    const float* user_emb = (const float*)d_in[0];
    const float* item_emb = (const float*)d_in[1];
    const int*   neg_idx  = (const int*)d_in[2];
    float*       out      = (float*)d_out;

    quantize_rows_kernel<<<2 * BN / 8, 256>>>(item_emb, user_emb);
    u2i_loss_kernel<<<GRID, 128>>>(neg_idx, out);
}

// round 17
// speedup vs baseline: 1.4221x; 1.1404x over previous
#include <cuda_runtime.h>

// Problem constants (fixed by the reference).
#define BN 4096
#define DN 768
#define KN 60
#define NLOGITS 61   // [pos, 60 negs]
#define NW 192       // int32 words per row (768 int8)
#define ROWS_PER_CTA 4
#define GRID (BN / ROWS_PER_CTA)   // 1024

// Scratch (__device__ globals: no allocation allowed).
__device__ __align__(256) int g_item_i8[BN * NW];   // 3 MB int8 item table
__device__ __align__(256) int g_user_i8[BN * NW];   // 3 MB int8 user table
__device__ float g_item_scale[BN];                  // per-row max/127
__device__ float g_user_scale[BN];
__device__ float g_row_loss[BN];
__device__ int   g_ctr = 0;

// ---------------------------------------------------------------------------
// Prologue: per-row symmetric int8 quantization of BOTH tables (R12 version).
// One warp per row; gwarp < BN -> item row, else user row.
// ---------------------------------------------------------------------------
__global__ void __launch_bounds__(256)
quantize_rows_kernel(const float* __restrict__ item_emb,
                     const float* __restrict__ user_emb)
{
    const int gwarp = (blockIdx.x * 256 + threadIdx.x) >> 5;   // 0 .. 2*BN-1
    const int lane  = threadIdx.x & 31;

    const float* src;
    int*   dst;
    float* sc;
    if (gwarp < BN) {
        src = item_emb + (size_t)gwarp * DN;
        dst = g_item_i8 + (size_t)gwarp * NW;
        sc  = &g_item_scale[gwarp];
    } else {
        const int r = gwarp - BN;
        src = user_emb + (size_t)r * DN;
        dst = g_user_i8 + (size_t)r * NW;
        sc  = &g_user_scale[r];
    }

    const float4* s4 = reinterpret_cast<const float4*>(src);
    float4 v[6];
    float m = 0.0f;
    #pragma unroll
    for (int t = 0; t < 6; ++t) {
        v[t] = __ldg(&s4[t * 32 + lane]);
        m = fmaxf(m, fmaxf(fmaxf(fabsf(v[t].x), fabsf(v[t].y)),
                           fmaxf(fabsf(v[t].z), fabsf(v[t].w))));
    }
    #pragma unroll
    for (int o = 16; o > 0; o >>= 1)
        m = fmaxf(m, __shfl_xor_sync(0xffffffffu, m, o));
    m = fmaxf(m, 1e-20f);
    const float inv = 127.0f / m;

    #pragma unroll
    for (int t = 0; t < 6; ++t) {
        const int qx = __float2int_rn(v[t].x * inv);
        const int qy = __float2int_rn(v[t].y * inv);
        const int qz = __float2int_rn(v[t].z * inv);
        const int qw = __float2int_rn(v[t].w * inv);
        dst[t * 32 + lane] = (qx & 0xFF) | ((qy & 0xFF) << 8) |
                             ((qz & 0xFF) << 16) | (qw << 24);
    }
    if (lane == 0) *sc = m / 127.0f;
}

// ---------------------------------------------------------------------------
// Main: ONE WARP PER ROW (R12 structure). 16 quad-logit iterations,
// constant trip count, fully unrolled. 12 front-batched LDG.64s per
// iteration; merged 9-shfl reduction for 4 exact int sums
// (results on lanes 0/16/8/24). In-warp logsumexp.
// ---------------------------------------------------------------------------
__global__ void __launch_bounds__(128, 6)
u2i_loss_kernel(const int* __restrict__ neg_idx,
                float*     __restrict__ out)
{
    __shared__ int   s_idx[ROWS_PER_CTA * 64];
    __shared__ float s_scale[ROWS_PER_CTA * 64];
    __shared__ float slog[ROWS_PER_CTA * 64];
    __shared__ int   s_last;

    const int tid  = threadIdx.x;
    const int warp = tid >> 5;
    const int lane = tid & 31;
    const int row  = blockIdx.x * ROWS_PER_CTA + warp;
    const int base = warp * 64;

    // Per-warp prologue: 61 indices + scales into warp-private smem.
    if (lane < 30) {
        const int2 v = __ldg(reinterpret_cast<const int2*>(neg_idx + (size_t)row * KN + 2 * lane));
        s_idx[base + 1 + 2 * lane] = v.x;
        s_idx[base + 2 + 2 * lane] = v.y;
        s_scale[base + 1 + 2 * lane] = __ldg(&g_item_scale[v.x]);
        s_scale[base + 2 + 2 * lane] = __ldg(&g_item_scale[v.y]);
    } else if (lane == 30) {
        s_idx[base] = row;                             // logit 0 = positive
        s_scale[base] = __ldg(&g_item_scale[row]);
    } else {
        s_idx[base + 61] = 0; s_idx[base + 62] = 0; s_idx[base + 63] = 0;
        slog[base + 61] = -3.0e38f;
        slog[base + 62] = -3.0e38f;
        slog[base + 63] = -3.0e38f;
    }

    // User slice: 6 int32 words (3 x LDG.64) + scale.
    const int2* uq2 = reinterpret_cast<const int2*>(g_user_i8 + (size_t)row * NW);
    int u[6];
    #pragma unroll
    for (int t = 0; t < 3; ++t) {
        const int2 w = __ldg(&uq2[t * 32 + lane]);
        u[2 * t]     = w.x;
        u[2 * t + 1] = w.y;
    }
    const float su = __ldg(&g_user_scale[row]);
    __syncwarp();

    // 16 quad-iterations: logits (4p, 4p+1, 4p+2, 4p+3); p=15 covers logit
    // 60 + three store-predicated pads (gather row 0).
    #pragma unroll
    for (int p = 0; p < 16; ++p) {
        const int jA = 4 * p;
        const int jB = 4 * p + 1;
        const int jC = 4 * p + 2;
        const int jD = 4 * p + 3;

        const int2* pA = reinterpret_cast<const int2*>(g_item_i8 + (size_t)s_idx[base + jA] * NW);
        const int2* pB = reinterpret_cast<const int2*>(g_item_i8 + (size_t)s_idx[base + jB] * NW);
        const int2* pC = reinterpret_cast<const int2*>(g_item_i8 + (size_t)s_idx[base + jC] * NW);
        const int2* pD = reinterpret_cast<const int2*>(g_item_i8 + (size_t)s_idx[base + jD] * NW);

        const int2 a0 = __ldg(&pA[lane]);
        const int2 a1 = __ldg(&pA[32 + lane]);
        const int2 a2 = __ldg(&pA[64 + lane]);
        const int2 b0 = __ldg(&pB[lane]);
        const int2 b1 = __ldg(&pB[32 + lane]);
        const int2 b2 = __ldg(&pB[64 + lane]);
        const int2 c0 = __ldg(&pC[lane]);
        const int2 c1 = __ldg(&pC[32 + lane]);
        const int2 c2 = __ldg(&pC[64 + lane]);
        const int2 d0 = __ldg(&pD[lane]);
        const int2 d1 = __ldg(&pD[32 + lane]);
        const int2 d2 = __ldg(&pD[64 + lane]);

        int accA = 0, accB = 0, accC = 0, accD = 0;
        accA = __dp4a(a0.x, u[0], accA);
        accA = __dp4a(a0.y, u[1], accA);
        accA = __dp4a(a1.x, u[2], accA);
        accA = __dp4a(a1.y, u[3], accA);
        accA = __dp4a(a2.x, u[4], accA);
        accA = __dp4a(a2.y, u[5], accA);
        accB = __dp4a(b0.x, u[0], accB);
        accB = __dp4a(b0.y, u[1], accB);
        accB = __dp4a(b1.x, u[2], accB);
        accB = __dp4a(b1.y, u[3], accB);
        accB = __dp4a(b2.x, u[4], accB);
        accB = __dp4a(b2.y, u[5], accB);
        accC = __dp4a(c0.x, u[0], accC);
        accC = __dp4a(c0.y, u[1], accC);
        accC = __dp4a(c1.x, u[2], accC);
        accC = __dp4a(c1.y, u[3], accC);
        accC = __dp4a(c2.x, u[4], accC);
        accC = __dp4a(c2.y, u[5], accC);
        accD = __dp4a(d0.x, u[0], accD);
        accD = __dp4a(d0.y, u[1], accD);
        accD = __dp4a(d1.x, u[2], accD);
        accD = __dp4a(d1.y, u[3], accD);
        accD = __dp4a(d2.x, u[4], accD);
        accD = __dp4a(d2.y, u[5], accD);

        // Merged reduction: 9 shfls for 4 exact int sums.
        accA += __shfl_xor_sync(0xffffffffu, accA, 16);
        accB += __shfl_xor_sync(0xffffffffu, accB, 16);
        accC += __shfl_xor_sync(0xffffffffu, accC, 16);
        accD += __shfl_xor_sync(0xffffffffu, accD, 16);
        int v1 = (lane < 16) ? accA : accB;
        int v2 = (lane < 16) ? accC : accD;
        v1 += __shfl_xor_sync(0xffffffffu, v1, 8);
        v2 += __shfl_xor_sync(0xffffffffu, v2, 8);
        int w = ((lane & 8) == 0) ? v1 : v2;
        w += __shfl_xor_sync(0xffffffffu, w, 4);
        w += __shfl_xor_sync(0xffffffffu, w, 2);
        w += __shfl_xor_sync(0xffffffffu, w, 1);
        // Full sums: A on lanes 0-7, C on 8-15, B on 16-23, D on 24-31.

        if (lane == 0)                   slog[base + jA] = (float)w * su * s_scale[base + jA];
        if (lane == 16 && jB < NLOGITS)  slog[base + jB] = (float)w * su * s_scale[base + jB];
        if (lane == 8  && jC < NLOGITS)  slog[base + jC] = (float)w * su * s_scale[base + jC];
        if (lane == 24 && jD < NLOGITS)  slog[base + jD] = (float)w * su * s_scale[base + jD];
    }
    __syncwarp();

    // In-warp stable logsumexp over 61 logits (2 per lane; 62..63 = -inf).
    {
        const float l0 = slog[base + lane];
        const float l1 = slog[base + lane + 32];
        float mm = fmaxf(l0, l1);
        #pragma unroll
        for (int o = 16; o > 0; o >>= 1)
            mm = fmaxf(mm, __shfl_xor_sync(0xffffffffu, mm, o));
        float s = expf(l0 - mm) + ((lane + 32 < NLOGITS) ? expf(l1 - mm) : 0.0f);
        #pragma unroll
        for (int o = 16; o > 0; o >>= 1)
            s += __shfl_xor_sync(0xffffffffu, s, o);
        if (lane == 0) {
            g_row_loss[row] = logf(s) + mm - slog[base];
            __threadfence();                            // release this row's loss
        }
    }
    __syncthreads();

    // CTA ticket; the last CTA performs the deterministic mean.
    if (tid == 0) {
        __threadfence();
        const int t = atomicAdd(&g_ctr, 1);
        s_last = (t == GRID - 1);
    }
    __syncthreads();

    if (s_last) {
        __threadfence();
        __shared__ float sred[128];
        float a = 0.0f;
        #pragma unroll
        for (int i = tid; i < BN; i += 128) a += g_row_loss[i];
        sred[tid] = a;
        __syncthreads();
        #pragma unroll
        for (int st = 64; st > 0; st >>= 1) {
            if (tid < st) sred[tid] += sred[tid + st];
            __syncthreads();
        }
        if (tid == 0) {
            out[0] = sred[0] * (1.0f / (float)BN);
            g_ctr = 0;                                 // reset for next graph replay
        }
    }
}

extern "C" void kernel_launch(void* const* d_in, const int* in_sizes, int n_in,
                              void* d_out, int out_size)
{
    const float* user_emb = (const float*)d_in[0];
    const float* item_emb = (const float*)d_in[1];
    const int*   neg_idx  = (const int*)d_in[2];
    float*       out      = (float*)d_out;

    quantize_rows_kernel<<<2 * BN / 8, 256>>>(item_emb, user_emb);
    u2i_loss_kernel<<<GRID, 128>>>(neg_idx, out);
}